// round 4
// baseline (speedup 1.0000x reference)
#include <cuda_runtime.h>
#include <cuda_bf16.h>
#include <cstdint>

// Problem constants
#define NB      32
#define CIN     256
#define COUT    32
#define CTOT    288
#define HH      56
#define WW      56
#define HW      (HH*WW)          // 3136
#define EPSV    1e-5f

// Tile config
#define TW      28               // tile width  (56 = 2*28)
#define TH      8                // tile height (56 = 7*8)
#define CC      8                // channels per smem chunk
#define NTHREADS 224             // 28 cols * 2 row-groups * 4 oc-groups

// Scratch (device globals: no allocations allowed)
__device__ float g_scale[CIN];
__device__ float g_shift[CIN];
__device__ float g_wt[CIN * 9 * COUT];     // [c][tap][oc]

// ---------------------------------------------------------------------------
// Prep: fold BN into scale/shift, transpose conv weight OIHW -> [c][tap][oc]
// ---------------------------------------------------------------------------
__global__ void prep_kernel(const float* __restrict__ bw,
                            const float* __restrict__ bb,
                            const float* __restrict__ rm,
                            const float* __restrict__ rv,
                            const float* __restrict__ wsrc) {
    int i = blockIdx.x * blockDim.x + threadIdx.x;
    if (i < CIN) {
        float s = bw[i] * rsqrtf(rv[i] + EPSV);
        g_scale[i] = s;
        g_shift[i] = bb[i] - rm[i] * s;
    }
    if (i < CIN * 9 * COUT) {
        int oc  = i & 31;
        int t2  = i >> 5;
        int tap = t2 % 9;
        int c   = t2 / 9;
        // src OIHW: [oc][c][ky][kx], tap = ky*3+kx
        g_wt[i] = wsrc[(oc * CIN + c) * 9 + tap];
    }
}

// ---------------------------------------------------------------------------
// f32x2 helpers (sm_100+ packed fp32 FMA; ptxas never emits from C++)
// ---------------------------------------------------------------------------
__device__ __forceinline__ unsigned long long pack2(float lo, float hi) {
    unsigned long long r;
    asm("mov.b64 %0, {%1, %2};" : "=l"(r) : "f"(lo), "f"(hi));
    return r;
}
__device__ __forceinline__ void unpack2(unsigned long long v, float& lo, float& hi) {
    asm("mov.b64 {%0, %1}, %2;" : "=f"(lo), "=f"(hi) : "l"(v));
}
#define FMA2(accv, av, bv) \
    asm("fma.rn.f32x2 %0, %1, %2, %0;" : "+l"(accv) : "l"(av), "l"(bv))

// ---------------------------------------------------------------------------
// Fused BN+ReLU+3x3 conv, direct, smem-tiled, f32x2 accumulation.
// Grid: (2, 7, 32)  Block: 224
// Each thread: 1 column, 4 rows, 8 out-channels (row pairs packed in f32x2).
// ---------------------------------------------------------------------------
__global__ __launch_bounds__(NTHREADS, 2)
void conv_kernel(const float* __restrict__ in0, float* __restrict__ out) {
    __shared__ float  s_x[CC][TH + 2][32];        // halo tile, padded pitch 32
    __shared__ float2 s_w2[CC][9][COUT];          // (w,w) pre-duplicated

    const int n   = blockIdx.z;
    const int x0  = blockIdx.x * TW;
    const int y0  = blockIdx.y * TH;
    const int tid = threadIdx.x;
    const int tx  = tid % TW;            // 0..27
    const int g   = tid / TW;            // 0..7
    const int tyg = g & 1;               // 0..1  -> rows tyg*4 .. +3
    const int toc = g >> 1;              // 0..3  -> oc  toc*8 .. +7
    const int yl0 = tyg * 4;
    const int oc0 = toc * 8;

    const float* inN = in0 + (size_t)n * CTOT * HW;

    unsigned long long acc[8][2];
    #pragma unroll
    for (int j = 0; j < 8; ++j) { acc[j][0] = 0ull; acc[j][1] = 0ull; }

    for (int cc0 = 0; cc0 < CIN; cc0 += CC) {
        // ---- fill x tile (BN + ReLU applied on the fly), zero-pad halo ----
        for (int i = tid; i < CC * (TH + 2) * (TW + 2); i += NTHREADS) {
            int lx = i % (TW + 2);
            int t2 = i / (TW + 2);
            int ly = t2 % (TH + 2);
            int c  = t2 / (TH + 2);
            int gx = x0 + lx - 1;
            int gy = y0 + ly - 1;
            float v = 0.0f;
            if ((unsigned)gx < WW && (unsigned)gy < HH) {
                int ch = cc0 + c;
                float xin = inN[(size_t)ch * HW + gy * WW + gx];
                v = fmaxf(fmaf(xin, g_scale[ch], g_shift[ch]), 0.0f);
            }
            s_x[c][ly][lx] = v;
        }
        // ---- fill duplicated weights ----
        for (int i = tid; i < CC * 9 * COUT; i += NTHREADS) {
            float w = g_wt[cc0 * 9 * COUT + i];
            int oc  = i & 31;
            int t2  = i >> 5;
            int tap = t2 % 9;
            int c   = t2 / 9;
            s_w2[c][tap][oc] = make_float2(w, w);
        }
        __syncthreads();

        // ---- compute ----
        for (int c = 0; c < CC; ++c) {
            // column values: 6 rows x 3 dx
            float xv[6][3];
            #pragma unroll
            for (int r = 0; r < 6; ++r)
                #pragma unroll
                for (int d = 0; d < 3; ++d)
                    xv[r][d] = s_x[c][yl0 + r][tx + d];

            // packed vertical pairs P[d][k] = (xv[k], xv[k+1])
            unsigned long long P[3][5];
            #pragma unroll
            for (int d = 0; d < 3; ++d)
                #pragma unroll
                for (int k = 0; k < 5; ++k)
                    P[d][k] = pack2(xv[k][d], xv[k + 1][d]);

            #pragma unroll
            for (int e = 0; e < 3; ++e) {           // dy+1
                #pragma unroll
                for (int d = 0; d < 3; ++d) {       // dx+1
                    const ulonglong2* wp =
                        (const ulonglong2*)&s_w2[c][e * 3 + d][oc0];
                    ulonglong2 wA = wp[0];
                    ulonglong2 wB = wp[1];
                    ulonglong2 wC = wp[2];
                    ulonglong2 wD = wp[3];
                    unsigned long long pa = P[d][e];
                    unsigned long long pb = P[d][e + 2];
                    FMA2(acc[0][0], pa, wA.x); FMA2(acc[0][1], pb, wA.x);
                    FMA2(acc[1][0], pa, wA.y); FMA2(acc[1][1], pb, wA.y);
                    FMA2(acc[2][0], pa, wB.x); FMA2(acc[2][1], pb, wB.x);
                    FMA2(acc[3][0], pa, wB.y); FMA2(acc[3][1], pb, wB.y);
                    FMA2(acc[4][0], pa, wC.x); FMA2(acc[4][1], pb, wC.x);
                    FMA2(acc[5][0], pa, wC.y); FMA2(acc[5][1], pb, wC.y);
                    FMA2(acc[6][0], pa, wD.x); FMA2(acc[6][1], pb, wD.x);
                    FMA2(acc[7][0], pa, wD.y); FMA2(acc[7][1], pb, wD.y);
                }
            }
        }
        __syncthreads();
    }

    // ---- write conv result into channels [256:288] ----
    float* outN = out + (size_t)n * CTOT * HW;
    #pragma unroll
    for (int j = 0; j < 8; ++j) {
        int oc = oc0 + j;
        float* op = outN + (size_t)(CIN + oc) * HW + (y0 + yl0) * WW + (x0 + tx);
        float r0, r1, r2, r3;
        unpack2(acc[j][0], r0, r1);
        unpack2(acc[j][1], r2, r3);
        op[0 * WW] = r0;
        op[1 * WW] = r1;
        op[2 * WW] = r2;
        op[3 * WW] = r3;
    }
}

// ---------------------------------------------------------------------------
extern "C" void kernel_launch(void* const* d_in, const int* in_sizes, int n_in,
                              void* d_out, int out_size) {
    const float* all_features = (const float*)d_in[0];
    const float* bn_weight    = (const float*)d_in[1];
    const float* bn_bias      = (const float*)d_in[2];
    const float* running_mean = (const float*)d_in[3];
    const float* running_var  = (const float*)d_in[4];
    const float* conv_weight  = (const float*)d_in[5];
    float* out = (float*)d_out;

    // 1) pass-through copy of the whole tensor (conv region overwritten below)
    cudaMemcpyAsync(out, all_features, (size_t)out_size * sizeof(float),
                    cudaMemcpyDeviceToDevice, 0);

    // 2) fold BN + transpose weights
    prep_kernel<<<(CIN * 9 * COUT + 255) / 256, 256>>>(
        bn_weight, bn_bias, running_mean, running_var, conv_weight);

    // 3) fused conv
    dim3 grid(WW / TW, HH / TH, NB);
    conv_kernel<<<grid, NTHREADS>>>(all_features, out);
}

// round 8
// speedup vs baseline: 5.2461x; 5.2461x over previous
#include <cuda_runtime.h>
#include <cuda_fp16.h>
#include <cstdint>

// ---------------- problem constants ----------------
#define NB     32
#define CIN    256
#define COUT   32
#define CTOT   288
#define HH     56
#define WW     56
#define HW     3136
#define EPSV   1e-5f

// padded NHWC activation buffer: [n][py 58][px 58][c 256] fp16
#define PW       58
#define PPITCH   (PW*256)        // 14848 halfs per padded row
#define NPITCH   (PW*PPITCH)     // 861184 halfs per image

__device__ __half g_act[(size_t)NB * NPITCH];   // 55.1 MB
__device__ __half g_wt[COUT * 2304];            // [oc][tap*256+c]

// ---------------- PTX helpers (baseline PTX only; no sm_103a-accel features) ----
static __device__ __forceinline__ uint32_t smem_u32(const void* p) {
    uint32_t a;
    asm("{ .reg .u64 t; cvta.to.shared.u64 t, %1; cvt.u32.u64 %0, t; }"
        : "=r"(a) : "l"(p));
    return a;
}
static __device__ __forceinline__ void cp_async16(uint32_t dst, const void* src, int sz) {
    asm volatile("cp.async.cg.shared.global [%0], [%1], 16, %2;"
                 :: "r"(dst), "l"(src), "r"(sz) : "memory");
}
static __device__ __forceinline__ void ldsm_x4(uint32_t& r0, uint32_t& r1,
                                               uint32_t& r2, uint32_t& r3, uint32_t addr) {
    asm volatile("ldmatrix.sync.aligned.m8n8.x4.shared.b16 {%0,%1,%2,%3}, [%4];"
                 : "=r"(r0), "=r"(r1), "=r"(r2), "=r"(r3) : "r"(addr));
}
static __device__ __forceinline__ void mma16816(float* c, uint32_t a0, uint32_t a1,
                                                uint32_t a2, uint32_t a3,
                                                uint32_t b0, uint32_t b1) {
    asm volatile("mma.sync.aligned.m16n8k16.row.col.f32.f16.f16.f32 "
                 "{%0,%1,%2,%3}, {%4,%5,%6,%7}, {%8,%9}, {%0,%1,%2,%3};"
                 : "+f"(c[0]), "+f"(c[1]), "+f"(c[2]), "+f"(c[3])
                 : "r"(a0), "r"(a1), "r"(a2), "r"(a3), "r"(b0), "r"(b1));
}

// ---------------- kernel 1: zero the pad border of g_act ----------------
__global__ void zero_border_kernel() {
    int i = blockIdx.x * blockDim.x + threadIdx.x;
    if (i >= NB * 228 * 32) return;
    int seg = i & 31;
    int t   = i >> 5;
    int bp  = t % 228;
    int n   = t / 228;
    int py, px;
    if      (bp < 58)  { py = 0;            px = bp; }
    else if (bp < 116) { py = 57;           px = bp - 58; }
    else if (bp < 172) { py = bp - 116 + 1; px = 0; }
    else               { py = bp - 172 + 1; px = 57; }
    uint4* p = (uint4*)(g_act + (size_t)n * NPITCH + py * PPITCH + px * 256 + seg * 8);
    *p = make_uint4(0u, 0u, 0u, 0u);
}

// ---------------- kernel 2: weight transform OIHW -> [oc][tap*256+c] fp16 ----------
__global__ void wtrans_kernel(const float* __restrict__ w) {
    int i = blockIdx.x * blockDim.x + threadIdx.x;
    if (i >= COUT * 2304) return;
    int oc = i / 2304;
    int k  = i % 2304;
    int t  = k >> 8;
    int c  = k & 255;
    g_wt[i] = __float2half(w[(oc * CIN + c) * 9 + t]);
}

// ---------------- kernel 3: passthrough + BN+ReLU -> padded NHWC fp16 ------------
__global__ __launch_bounds__(256) void stage1_kernel(
    const float* __restrict__ in, const float* __restrict__ bw,
    const float* __restrict__ bb, const float* __restrict__ rm,
    const float* __restrict__ rv, float* __restrict__ out) {
    __shared__ __half st[64][72];     // [pixel][channel], 144B pitch (16B aligned)
    __shared__ float ss[64], sh[64];

    int pb = blockIdx.x, cb = blockIdx.y, n = blockIdx.z;
    int tid = threadIdx.x;
    if (tid < 64) {
        int c = cb * 64 + tid;
        float s = bw[c] * rsqrtf(rv[c] + EPSV);
        ss[tid] = s;
        sh[tid] = bb[c] - rm[c] * s;
    }
    __syncthreads();

    int ci0 = tid >> 4, pj = tid & 15;
    int p0 = pb * 64;
    #pragma unroll
    for (int r = 0; r < 4; r++) {
        int c = r * 16 + ci0;
        size_t off = ((size_t)n * CTOT + cb * 64 + c) * HW + p0;
        float4 v = ((const float4*)(in + off))[pj];
        ((float4*)(out + off))[pj] = v;                 // passthrough (original values)
        float s = ss[c], h = sh[c];
        st[pj * 4 + 0][c] = __float2half(fmaxf(fmaf(v.x, s, h), 0.f));
        st[pj * 4 + 1][c] = __float2half(fmaxf(fmaf(v.y, s, h), 0.f));
        st[pj * 4 + 2][c] = __float2half(fmaxf(fmaf(v.z, s, h), 0.f));
        st[pj * 4 + 3][c] = __float2half(fmaxf(fmaf(v.w, s, h), 0.f));
    }
    __syncthreads();

    #pragma unroll
    for (int r = 0; r < 2; r++) {
        int e = r * 256 + tid;
        int p = e >> 3, seg = e & 7;
        int P = p0 + p;
        int y = P / 56, x = P % 56;
        uint4 v = *(uint4*)&st[p][seg * 8];
        *(uint4*)(g_act + (size_t)n * NPITCH + (y + 1) * PPITCH + (x + 1) * 256
                  + cb * 64 + seg * 8) = v;
    }
}

// ---------------- kernel 4: implicit-GEMM conv via ldmatrix + mma.sync ------------
// CTA: 256 threads (8 warps). Tile: M=128 pixels (2 rows x 64 cols), N=32 oc,
// K=2304 in 36 chunks of 64 (tap x 64-channel group). 4-stage cp.async pipeline.
#define SLOTS    4
#define CHUNKS   36
#define ABYTES   16384            // A: 128 rows x 128B (SW128 swizzled)
#define STAGEB   20480            // A + B(32 rows x 128B)
#define CONV_SMEM (SLOTS * STAGEB)   // 81920

static __device__ __forceinline__ void load_chunk(int chunk, int slot, uint32_t sb,
                                                  const __half* actN, int y0, int tid) {
    int t  = chunk >> 2;              // tap 0..8
    int cg = chunk & 3;               // channel group
    int dy = t / 3, dx = t - dy * 3;
    int c0 = cg << 6;
    int seg = tid & 7, tg = tid >> 3; // seg: 16B segment, tg: 0..31

    uint32_t A = sb + slot * STAGEB;
    const __half* base = actN + (y0 + dy) * PPITCH + dx * 256 + c0 + seg * 8;
    #pragma unroll
    for (int r = 0; r < 4; r++) {
        int m  = tg + r * 32;         // A row = output pixel index (yy*64+xx)
        int yy = m >> 6, xx = m & 63;
        const void* src = base + yy * PPITCH + xx * 256;
        uint32_t off = m * 128 + seg * 16;
        uint32_t dst = A + (off ^ ((m & 7) << 4));     // SW128 swizzle
        int sz = (xx + dx <= 57) ? 16 : 0;             // zero-fill beyond padded width
        cp_async16(dst, src, sz);
    }
    // B: 32 oc rows x 64 halfs, one 16B segment per thread
    uint32_t B = A + ABYTES;
    uint32_t off = tg * 128 + seg * 16;
    uint32_t dst = B + (off ^ ((tg & 7) << 4));
    cp_async16(dst, g_wt + tg * 2304 + t * 256 + c0 + seg * 8, 16);
}

__global__ __launch_bounds__(256, 2)
void conv_kernel(float* __restrict__ out) {
    extern __shared__ __align__(128) char smem[];
    uint32_t sb = smem_u32(smem);
    int tid  = threadIdx.x;
    int w    = tid >> 5;              // warp 0..7 -> m rows [w*16, w*16+16)
    int lane = tid & 31;
    int bx = blockIdx.x;
    int n  = bx / 28;
    int y0 = (bx % 28) * 2;
    const __half* actN = g_act + (size_t)n * NPITCH;

    float acc[4][4];                  // [nblock][c0..c3]
    #pragma unroll
    for (int i = 0; i < 4; i++)
        #pragma unroll
        for (int j = 0; j < 4; j++) acc[i][j] = 0.f;

    // prologue: 3 stages in flight
    #pragma unroll
    for (int s = 0; s < SLOTS - 1; s++) {
        load_chunk(s, s, sb, actN, y0, tid);
        asm volatile("cp.async.commit_group;" ::: "memory");
    }

    // precomputed fragment addresses (relative to slot base)
    int ar  = w * 16 + (lane & 15);                     // A row for this lane
    uint32_t aoff = (uint32_t)(ar * 128) ^ ((ar & 7) << 4);
    int asegbase = (lane >> 4);                         // 0/1 -> +16B within k-step
    int bn1 = ((lane >> 4) & 1) * 8 + (lane & 7);       // B rows for x4 #1 (n 0..15)
    uint32_t boff1 = (uint32_t)(bn1 * 128) ^ ((bn1 & 7) << 4);
    int bn2 = bn1 + 16;                                 // B rows for x4 #2 (n 16..31)
    uint32_t boff2 = (uint32_t)(bn2 * 128) ^ ((bn2 & 7) << 4);
    int bseg = (lane >> 3) & 1;                         // k half within k-step

    for (int i = 0; i < CHUNKS; i++) {
        asm volatile("cp.async.wait_group 2;" ::: "memory");   // chunk i resident
        __syncthreads();

        if (i + SLOTS - 1 < CHUNKS)
            load_chunk(i + SLOTS - 1, (i + SLOTS - 1) % SLOTS, sb, actN, y0, tid);
        asm volatile("cp.async.commit_group;" ::: "memory");

        uint32_t A = sb + (i % SLOTS) * STAGEB;
        uint32_t B = A + ABYTES;
        #pragma unroll
        for (int kk = 0; kk < 4; kk++) {
            uint32_t a0, a1, a2, a3;
            ldsm_x4(a0, a1, a2, a3, A + (aoff ^ (uint32_t)((kk * 2 + asegbase) * 16)));
            uint32_t b00, b01, b10, b11;
            ldsm_x4(b00, b01, b10, b11, B + (boff1 ^ (uint32_t)((kk * 2 + bseg) * 16)));
            uint32_t b20, b21, b30, b31;
            ldsm_x4(b20, b21, b30, b31, B + (boff2 ^ (uint32_t)((kk * 2 + bseg) * 16)));
            mma16816(acc[0], a0, a1, a2, a3, b00, b01);
            mma16816(acc[1], a0, a1, a2, a3, b10, b11);
            mma16816(acc[2], a0, a1, a2, a3, b20, b21);
            mma16816(acc[3], a0, a1, a2, a3, b30, b31);
        }
    }

    // ---- epilogue: write channels [256:288] ----
    int mr = w * 16 + (lane >> 2);
    int nc = (lane & 3) * 2;
    float* obase = out + ((size_t)n * CTOT + CIN) * HW + y0 * WW;
    #pragma unroll
    for (int nb = 0; nb < 4; nb++) {
        #pragma unroll
        for (int h = 0; h < 2; h++) {
            int m  = mr + 8 * h;
            int yy = m >> 6, xx = m & 63;
            if (xx < 56) {
                float* p = obase + (size_t)(nb * 8 + nc) * HW + yy * WW + xx;
                p[0]  = acc[nb][2 * h + 0];
                p[HW] = acc[nb][2 * h + 1];
            }
        }
    }
}

// ---------------- launch ----------------
extern "C" void kernel_launch(void* const* d_in, const int* in_sizes, int n_in,
                              void* d_out, int out_size) {
    const float* all_features = (const float*)d_in[0];
    const float* bn_weight    = (const float*)d_in[1];
    const float* bn_bias      = (const float*)d_in[2];
    const float* running_mean = (const float*)d_in[3];
    const float* running_var  = (const float*)d_in[4];
    const float* conv_weight  = (const float*)d_in[5];
    float* out = (float*)d_out;

    static bool attr_set = false;
    if (!attr_set) {
        cudaFuncSetAttribute(conv_kernel,
                             cudaFuncAttributeMaxDynamicSharedMemorySize, CONV_SMEM);
        attr_set = true;
    }

    zero_border_kernel<<<(NB * 228 * 32 + 255) / 256, 256>>>();
    wtrans_kernel<<<(COUT * 2304 + 255) / 256, 256>>>(conv_weight);

    dim3 g1(49, 4, NB);   // 64-pixel blocks x 64-channel blocks x images
    stage1_kernel<<<g1, 256>>>(all_features, bn_weight, bn_bias,
                               running_mean, running_var, out);

    conv_kernel<<<NB * 28, 256, CONV_SMEM>>>(out);
}

// round 10
// speedup vs baseline: 6.6952x; 1.2762x over previous
#include <cuda_runtime.h>
#include <cuda_fp16.h>
#include <cstdint>

// ---------------- problem constants ----------------
#define NB     32
#define CIN    256
#define COUT   32
#define CTOT   288
#define HH     56
#define WW     56
#define HW     3136
#define EPSV   1e-5f

// padded NHWC activation buffer: [n][py 58][px 58][c 256] fp16
#define PW       58
#define PPITCH   (PW*256)        // 14848 halfs per padded row
#define NPITCH   (PW*PPITCH)     // 861184 halfs per image

__device__ __half g_act[(size_t)NB * NPITCH];   // 55.1 MB
__device__ __half g_wt[COUT * 2304];            // [oc][tap*256+c]

// ---------------- PTX helpers (baseline PTX only) ----------------
static __device__ __forceinline__ uint32_t smem_u32(const void* p) {
    uint32_t a;
    asm("{ .reg .u64 t; cvta.to.shared.u64 t, %1; cvt.u32.u64 %0, t; }"
        : "=r"(a) : "l"(p));
    return a;
}
static __device__ __forceinline__ void cp_async16(uint32_t dst, const void* src) {
    asm volatile("cp.async.cg.shared.global [%0], [%1], 16;"
                 :: "r"(dst), "l"(src) : "memory");
}
static __device__ __forceinline__ void ldsm_x4(uint32_t& r0, uint32_t& r1,
                                               uint32_t& r2, uint32_t& r3, uint32_t addr) {
    asm volatile("ldmatrix.sync.aligned.m8n8.x4.shared.b16 {%0,%1,%2,%3}, [%4];"
                 : "=r"(r0), "=r"(r1), "=r"(r2), "=r"(r3) : "r"(addr));
}
static __device__ __forceinline__ void mma16816(float* c, uint32_t a0, uint32_t a1,
                                                uint32_t a2, uint32_t a3,
                                                uint32_t b0, uint32_t b1) {
    asm volatile("mma.sync.aligned.m16n8k16.row.col.f32.f16.f16.f32 "
                 "{%0,%1,%2,%3}, {%4,%5,%6,%7}, {%8,%9}, {%0,%1,%2,%3};"
                 : "+f"(c[0]), "+f"(c[1]), "+f"(c[2]), "+f"(c[3])
                 : "r"(a0), "r"(a1), "r"(a2), "r"(a3), "r"(b0), "r"(b1));
}

// ---------------- kernel 1: prep (border zero + weight transform) ----------------
#define BORDER_THREADS (NB * 228 * 32)
__global__ void prep_kernel(const float* __restrict__ w) {
    int i = blockIdx.x * blockDim.x + threadIdx.x;
    if (i < BORDER_THREADS) {
        int seg = i & 31;
        int t   = i >> 5;
        int bp  = t % 228;
        int n   = t / 228;
        int py, px;
        if      (bp < 58)  { py = 0;            px = bp; }
        else if (bp < 116) { py = 57;           px = bp - 58; }
        else if (bp < 172) { py = bp - 116 + 1; px = 0; }
        else               { py = bp - 172 + 1; px = 57; }
        uint4* p = (uint4*)(g_act + (size_t)n * NPITCH + py * PPITCH + px * 256 + seg * 8);
        *p = make_uint4(0u, 0u, 0u, 0u);
    } else {
        int j = i - BORDER_THREADS;
        if (j < COUT * 2304) {
            int oc = j / 2304;
            int k  = j % 2304;
            int t  = k >> 8;
            int c  = k & 255;
            g_wt[j] = __float2half(w[(oc * CIN + c) * 9 + t]);
        }
    }
}

// ---------------- kernel 2: passthrough + BN+ReLU -> padded NHWC fp16 ------------
__global__ __launch_bounds__(256) void stage1_kernel(
    const float* __restrict__ in, const float* __restrict__ bw,
    const float* __restrict__ bb, const float* __restrict__ rm,
    const float* __restrict__ rv, float* __restrict__ out) {
    __shared__ __half st[64][72];     // [pixel][channel], 144B pitch
    __shared__ float ss[64], sh[64];

    int pb = blockIdx.x, cb = blockIdx.y, n = blockIdx.z;
    int tid = threadIdx.x;
    if (tid < 64) {
        int c = cb * 64 + tid;
        float s = bw[c] * rsqrtf(rv[c] + EPSV);
        ss[tid] = s;
        sh[tid] = bb[c] - rm[c] * s;
    }
    __syncthreads();

    int ci0 = tid >> 4, pj = tid & 15;
    int p0 = pb * 64;
    #pragma unroll
    for (int r = 0; r < 4; r++) {
        int c = r * 16 + ci0;
        size_t off = ((size_t)n * CTOT + cb * 64 + c) * HW + p0;
        float4 v = ((const float4*)(in + off))[pj];
        ((float4*)(out + off))[pj] = v;                 // passthrough
        float s = ss[c], h = sh[c];
        st[pj * 4 + 0][c] = __float2half(fmaxf(fmaf(v.x, s, h), 0.f));
        st[pj * 4 + 1][c] = __float2half(fmaxf(fmaf(v.y, s, h), 0.f));
        st[pj * 4 + 2][c] = __float2half(fmaxf(fmaf(v.z, s, h), 0.f));
        st[pj * 4 + 3][c] = __float2half(fmaxf(fmaf(v.w, s, h), 0.f));
    }
    __syncthreads();

    #pragma unroll
    for (int r = 0; r < 2; r++) {
        int e = r * 256 + tid;
        int p = e >> 3, seg = e & 7;
        int P = p0 + p;
        int y = P / 56, x = P % 56;
        uint4 v = *(uint4*)&st[p][seg * 8];
        *(uint4*)(g_act + (size_t)n * NPITCH + (y + 1) * PPITCH + (x + 1) * 256
                  + cb * 64 + seg * 8) = v;
    }
}

// ---------------- kernel 3: implicit-GEMM conv, tap-reuse in smem ----------------
// CTA: 256 threads (8 warps). Tile: M=256 pixels (4 out rows x 64 cols), N=32.
// K loop: 8 channel-groups (cg) of 32; per cg load 6 input rows x 58 px x 32 ch
// ONCE, sweep 9 taps as shifted ldmatrix windows. A/B double-buffered per cg.
#define ABUF   23040             // 360 px slots x 64B (348 used + read slack)
#define BBUF   18432             // 9 taps x 32 oc x 32 ch x 2B
#define BOFF   (2*ABUF)          // 46080
#define CONV_SMEM (2*ABUF + 2*BBUF)  // 82944

__device__ __constant__ int TAPOFF[9] = {0,1,2, 58,59,60, 116,117,118};

static __device__ __forceinline__ void load_cg(int cg, int buf, uint32_t sb,
                                               const __half* actN, int y0, int tid) {
    uint32_t A = sb + buf * ABUF;
    const __half* asrc0 = actN + (size_t)y0 * PPITCH + cg * 32;
    #pragma unroll
    for (int it = 0; it < 6; it++) {
        int i = tid + it * 256;
        if (i < 1392) {                       // 348 pixels x 4 segs
            int p = i >> 2, seg = i & 3;
            int r = p / 58, px = p - r * 58;
            const void* src = asrc0 + r * PPITCH + px * 256 + seg * 8;
            uint32_t dst = A + (((uint32_t)p * 64) ^ ((uint32_t)seg << 4)
                                ^ (((uint32_t)(p & 7)) << 4));
            cp_async16(dst, src);
        }
    }
    uint32_t B = sb + BOFF + buf * BBUF;
    #pragma unroll
    for (int it = 0; it < 5; it++) {
        int i = tid + it * 256;
        if (i < 1152) {                       // 9 taps x 32 oc x 4 segs
            int tap = i >> 7, rem = i & 127;
            int oc = rem >> 2, seg = rem & 3;
            const void* src = g_wt + oc * 2304 + tap * 256 + cg * 32 + seg * 8;
            uint32_t dst = B + tap * 2048 + (((uint32_t)oc * 64) ^ ((uint32_t)seg << 4)
                                             ^ (((uint32_t)(oc & 7)) << 4));
            cp_async16(dst, src);
        }
    }
}

__global__ __launch_bounds__(256, 2)
void conv_kernel(float* __restrict__ out) {
    extern __shared__ __align__(128) char smem[];
    uint32_t sb = smem_u32(smem);
    int tid  = threadIdx.x;
    int w    = tid >> 5;                      // warp 0..7 -> m rows [w*32, w*32+32)
    int lane = tid & 31;
    int bx = blockIdx.x;
    int n  = bx / 14;
    int y0 = (bx % 14) * 4;                   // 4 output rows per CTA
    const __half* actN = g_act + (size_t)n * NPITCH;

    float acc[2][4][4];
    #pragma unroll
    for (int mt = 0; mt < 2; mt++)
        #pragma unroll
        for (int nb = 0; nb < 4; nb++)
            #pragma unroll
            for (int j = 0; j < 4; j++) acc[mt][nb][j] = 0.f;

    // per-lane fragment geometry
    int pb[2];
    #pragma unroll
    for (int mt = 0; mt < 2; mt++) {
        int m  = w * 32 + mt * 16 + (lane & 15);
        int yy = m >> 6, xx = m & 63;
        pb[mt] = yy * 58 + xx;
    }
    uint32_t aseg = (uint32_t)(lane >> 4);              // 0/1: k-half within k16
    int bn1 = ((lane >> 4) & 1) * 8 + (lane & 7);       // B rows n0-15
    int bn2 = bn1 + 16;                                 // B rows n16-31
    uint32_t bsw  = ((uint32_t)(lane & 7)) << 4;
    uint32_t bo1  = ((uint32_t)bn1 * 64) ^ bsw;
    uint32_t bo2  = ((uint32_t)bn2 * 64) ^ bsw;
    uint32_t bseg = (uint32_t)((lane >> 3) & 1);

    // prologue: two cg stages in flight
    load_cg(0, 0, sb, actN, y0, tid);
    asm volatile("cp.async.commit_group;" ::: "memory");
    load_cg(1, 1, sb, actN, y0, tid);
    asm volatile("cp.async.commit_group;" ::: "memory");

    for (int cg = 0; cg < 8; cg++) {
        asm volatile("cp.async.wait_group 1;" ::: "memory");
        __syncthreads();

        uint32_t A = sb + (cg & 1) * ABUF;
        uint32_t B = sb + BOFF + (cg & 1) * BBUF;

        #pragma unroll
        for (int tap = 0; tap < 9; tap++) {
            uint32_t abase[2];
            #pragma unroll
            for (int mt = 0; mt < 2; mt++) {
                uint32_t p = (uint32_t)(pb[mt] + TAPOFF[tap]);
                abase[mt] = A + ((p * 64) ^ ((p & 7) << 4));
            }
            uint32_t Bt = B + tap * 2048;
            #pragma unroll
            for (int kk = 0; kk < 2; kk++) {
                uint32_t ksel = ((uint32_t)kk * 2) << 4;
                uint32_t a[2][4];
                #pragma unroll
                for (int mt = 0; mt < 2; mt++)
                    ldsm_x4(a[mt][0], a[mt][1], a[mt][2], a[mt][3],
                            abase[mt] ^ (ksel ^ (aseg << 4)));
                uint32_t b00, b01, b10, b11, b20, b21, b30, b31;
                ldsm_x4(b00, b01, b10, b11, Bt + (bo1 ^ (ksel ^ (bseg << 4))));
                ldsm_x4(b20, b21, b30, b31, Bt + (bo2 ^ (ksel ^ (bseg << 4))));
                #pragma unroll
                for (int mt = 0; mt < 2; mt++) {
                    mma16816(acc[mt][0], a[mt][0], a[mt][1], a[mt][2], a[mt][3], b00, b01);
                    mma16816(acc[mt][1], a[mt][0], a[mt][1], a[mt][2], a[mt][3], b10, b11);
                    mma16816(acc[mt][2], a[mt][0], a[mt][1], a[mt][2], a[mt][3], b20, b21);
                    mma16816(acc[mt][3], a[mt][0], a[mt][1], a[mt][2], a[mt][3], b30, b31);
                }
            }
        }
        __syncthreads();
        if (cg + 2 < 8)
            load_cg(cg + 2, cg & 1, sb, actN, y0, tid);
        asm volatile("cp.async.commit_group;" ::: "memory");
    }

    // ---- epilogue: write channels [256:288] ----
    float* obase = out + ((size_t)n * CTOT + CIN) * HW + y0 * WW;
    int nc = (lane & 3) * 2;
    #pragma unroll
    for (int mt = 0; mt < 2; mt++) {
        int m0 = w * 32 + mt * 16 + (lane >> 2);
        #pragma unroll
        for (int nb = 0; nb < 4; nb++) {
            #pragma unroll
            for (int h = 0; h < 2; h++) {
                int m  = m0 + 8 * h;
                int yy = m >> 6, xx = m & 63;
                if (xx < 56) {
                    float* p = obase + (size_t)(nb * 8 + nc) * HW + yy * WW + xx;
                    p[0]  = acc[mt][nb][2 * h + 0];
                    p[HW] = acc[mt][nb][2 * h + 1];
                }
            }
        }
    }
}

// ---------------- launch ----------------
extern "C" void kernel_launch(void* const* d_in, const int* in_sizes, int n_in,
                              void* d_out, int out_size) {
    const float* all_features = (const float*)d_in[0];
    const float* bn_weight    = (const float*)d_in[1];
    const float* bn_bias      = (const float*)d_in[2];
    const float* running_mean = (const float*)d_in[3];
    const float* running_var  = (const float*)d_in[4];
    const float* conv_weight  = (const float*)d_in[5];
    float* out = (float*)d_out;

    static bool attr_set = false;
    if (!attr_set) {
        cudaFuncSetAttribute(conv_kernel,
                             cudaFuncAttributeMaxDynamicSharedMemorySize, CONV_SMEM);
        attr_set = true;
    }

    prep_kernel<<<(BORDER_THREADS + COUT * 2304 + 255) / 256, 256>>>(conv_weight);

    dim3 g1(49, 4, NB);   // 64-pixel blocks x 64-channel blocks x images
    stage1_kernel<<<g1, 256>>>(all_features, bn_weight, bn_bias,
                               running_mean, running_var, out);

    conv_kernel<<<NB * 14, 256, CONV_SMEM>>>(out);
}